// round 1
// baseline (speedup 1.0000x reference)
#include <cuda_runtime.h>
#include <math.h>

#define T_LEN 4096
#define B_SZ  16

// ---------------- scratch (device globals; no allocation allowed) ----------------
__device__ float g_bufA[16*512*4096];
__device__ float g_bufB[16*512*4096];
__device__ float g_ye  [16*128*4096];
__device__ float g_z   [16*64*4096];
__device__ float g_zvq [16*64*4096];
__device__ float g_wt  [640*5*1024];
__device__ float g_cbt [64*512];
__device__ float g_cbn [512];
__device__ float g_spk [128*128];
__device__ int   g_idx [16*4096];

// ---------------- small helper kernels ----------------
__global__ void transpose_x_k(const float* __restrict__ x, float* __restrict__ xt) {
    __shared__ float tile[32][33];
    int b = blockIdx.z;
    int t0 = blockIdx.x*32, f0 = blockIdx.y*32;
    int tx = threadIdx.x, ty = threadIdx.y;
    for (int j = ty; j < 32; j += 8) {
        int t = t0 + j, f = f0 + tx;
        tile[j][tx] = (f < 80) ? x[((size_t)b*T_LEN + t)*80 + f] : 0.f;
    }
    __syncthreads();
    for (int j = ty; j < 32; j += 8) {
        int f = f0 + j, t = t0 + tx;
        if (f < 80) xt[((size_t)b*80 + f)*T_LEN + t] = tile[tx][j];
    }
}

__global__ void spknorm_k(const float* __restrict__ spk, float* __restrict__ o) {
    __shared__ float red[128];
    int r = blockIdx.x, t = threadIdx.x;
    float v = spk[r*128 + t];
    red[t] = v*v;
    __syncthreads();
    for (int s = 64; s > 0; s >>= 1) { if (t < s) red[t] += red[t+s]; __syncthreads(); }
    o[r*128 + t] = v * rsqrtf(red[0]);
}

__global__ void cbnorm_k(const float* __restrict__ cb, float* __restrict__ n) {
    int c = blockIdx.x*128 + threadIdx.x;
    if (c < 512) {
        float s = 0.f;
        for (int d = 0; d < 64; d++) { float v = cb[c*64 + d]; s += v*v; }
        n[c] = s;
    }
}

__global__ void ye_gather_k(const int* __restrict__ y, const float* __restrict__ spk,
                            float* __restrict__ ye) {
    int b = blockIdx.y;
    int t = blockIdx.x*32 + (threadIdx.x & 31);
    int w = threadIdx.x >> 5;
    int yi = y[(size_t)b*T_LEN + t];
    for (int c = w; c < 128; c += 8)
        ye[((size_t)b*128 + c)*T_LEN + t] = spk[yi*128 + c];
}

__global__ void zvq_gather_k(const int* __restrict__ idx, const float* __restrict__ cb,
                             float* __restrict__ zvq) {
    int b = blockIdx.y;
    int t = blockIdx.x*32 + (threadIdx.x & 31);
    int w = threadIdx.x >> 5;
    int ii = idx[(size_t)b*T_LEN + t];
    for (int d = w; d < 64; d += 8)
        zvq[((size_t)b*64 + d)*T_LEN + t] = cb[ii*64 + d];
}

// weight transform -> wt[ci][k][co] contiguous (dec=1 also does ConvT flip/transpose)
__global__ void wtrans_k(const float* __restrict__ w, float* __restrict__ wt,
                         int CIN, int COUT, int K, int dec) {
    int e = blockIdx.x*256 + threadIdx.x;
    int total = CIN*COUT*K;
    if (e >= total) return;
    int co = e % COUT; int r = e / COUT; int k = r % K; int ci = r / K;
    wt[e] = dec ? w[((size_t)ci*COUT + co)*K + (K-1-k)]
                : w[((size_t)co*CIN + ci)*K + k];
}

// ---------------- generic fused conv kernel ----------------
// EPI: 0=bias only ([b][co][t]), 1=LN+LeakyReLU, 2=LN+GLU (writes COUT/2 ch),
//      3=VQ argmin (bias=||c||^2, writes int idx), 4=bias only transposed ([b][t][co])
template<int CIN1,int CIN2,int COUT,int KS,int CI_BLK,int G_CO,int TPT,int EPI>
__global__ __launch_bounds__(256,2) void conv_k(
    const float* __restrict__ in1, const float* __restrict__ in2,
    const float* __restrict__ wt, const float* __restrict__ bias,
    const float* __restrict__ gamma, const float* __restrict__ beta,
    float* __restrict__ out, int* __restrict__ oidx)
{
    constexpr int CIN  = CIN1 + CIN2;
    constexpr int PAD  = (KS - 1) / 2;
    constexpr int G_T  = 256 / G_CO;
    constexpr int TT   = G_T * TPT;
    constexpr int CPT  = COUT / G_CO;
    constexpr int RIN  = TPT + KS - 1;
    constexpr int IROW = TT + KS - 1;
    constexpr int WELEMS = CI_BLK * KS * COUT;
    constexpr int IELEMS = CI_BLK * IROW;
    constexpr int NCB  = CIN / CI_BLK;
    constexpr bool NEED_RED = (EPI==1 || EPI==2 || EPI==3);
    constexpr int RSTRIDE = G_CO + 1;

    extern __shared__ float smem[];
    float* sW = smem;
    float* sI = sW + WELEMS;
    float* sRa = sI + IELEMS;                 // TT*RSTRIDE
    float* sRb = sRa + (NEED_RED ? TT*RSTRIDE : 0);
    float* sMean = sRb + (NEED_RED ? TT*RSTRIDE : 0);
    float* sRstd = sMean + (NEED_RED ? TT : 0);

    const int tid = threadIdx.x;
    const int cg  = tid % G_CO;
    const int tg  = tid / G_CO;
    const int b   = blockIdx.y;
    const int t0  = blockIdx.x * TT;

    float acc[CPT][TPT];
    #pragma unroll
    for (int i = 0; i < CPT; i++)
        #pragma unroll
        for (int t = 0; t < TPT; t++) acc[i][t] = 0.f;

    for (int cb = 0; cb < NCB; cb++) {
        __syncthreads();
        const float* wsrc = wt + (size_t)cb * WELEMS;
        for (int e = tid; e < WELEMS; e += 256) sW[e] = wsrc[e];
        for (int e = tid; e < IELEMS; e += 256) {
            int ci = e / IROW, j = e % IROW;
            int t  = t0 - PAD + j;
            int cig = cb*CI_BLK + ci;
            float v = 0.f;
            if (t >= 0 && t < T_LEN) {
                if (CIN2 == 0 || cig < CIN1)
                    v = in1[((size_t)b*CIN1 + cig)*T_LEN + t];
                else
                    v = in2[((size_t)b*CIN2 + (cig - CIN1))*T_LEN + t];
            }
            sI[e] = v;
        }
        __syncthreads();

        #pragma unroll 1
        for (int ci = 0; ci < CI_BLK; ci++) {
            float rin[RIN];
            #pragma unroll
            for (int j = 0; j < RIN; j++) rin[j] = sI[ci*IROW + tg*TPT + j];
            #pragma unroll
            for (int k = 0; k < KS; k++) {
                #pragma unroll
                for (int i = 0; i < CPT; i++) {
                    float wv = sW[(ci*KS + k)*COUT + cg + G_CO*i];
                    #pragma unroll
                    for (int t = 0; t < TPT; t++)
                        acc[i][t] = fmaf(wv, rin[t + k], acc[i][t]);
                }
            }
        }
    }

    if constexpr (EPI == 3) {
        // VQ argmin: score = ||c||^2 - 2 * (z . c)
        float bv[CPT];
        #pragma unroll
        for (int i = 0; i < CPT; i++) bv[i] = bias[cg + G_CO*i];
        int* sRi = (int*)sRb;
        #pragma unroll
        for (int t = 0; t < TPT; t++) {
            float best = 3.4e38f; int bi = 0;
            #pragma unroll
            for (int i = 0; i < CPT; i++) {
                float v = bv[i] - 2.f*acc[i][t];
                int ii = cg + G_CO*i;
                if (v < best || (v == best && ii < bi)) { best = v; bi = ii; }
            }
            int tl = tg*TPT + t;
            sRa[tl*RSTRIDE + cg] = best;
            sRi[tl*RSTRIDE + cg] = bi;
        }
        __syncthreads();
        if (tid < TT) {
            float best = 3.4e38f; int bi = 0;
            for (int g = 0; g < G_CO; g++) {
                float v = sRa[tid*RSTRIDE + g]; int ii = sRi[tid*RSTRIDE + g];
                if (v < best || (v == best && ii < bi)) { best = v; bi = ii; }
            }
            oidx[(size_t)b*T_LEN + t0 + tid] = bi;
        }
        return;
    } else {
        // add conv bias
        #pragma unroll
        for (int i = 0; i < CPT; i++) {
            float bv = bias[cg + G_CO*i];
            #pragma unroll
            for (int t = 0; t < TPT; t++) acc[i][t] += bv;
        }

        if constexpr (EPI == 1 || EPI == 2) {
            #pragma unroll
            for (int t = 0; t < TPT; t++) {
                float s = 0.f, q = 0.f;
                #pragma unroll
                for (int i = 0; i < CPT; i++) { float v = acc[i][t]; s += v; q += v*v; }
                int tl = tg*TPT + t;
                sRa[tl*RSTRIDE + cg] = s;
                sRb[tl*RSTRIDE + cg] = q;
            }
            __syncthreads();
            if (tid < TT) {
                float s = 0.f, q = 0.f;
                for (int g = 0; g < G_CO; g++) { s += sRa[tid*RSTRIDE + g]; q += sRb[tid*RSTRIDE + g]; }
                float m = s * (1.f/COUT);
                float v = q * (1.f/COUT) - m*m;
                sMean[tid] = m;
                sRstd[tid] = rsqrtf(v + 1e-5f);
            }
            __syncthreads();

            if constexpr (EPI == 1) {
                #pragma unroll
                for (int i = 0; i < CPT; i++) {
                    int co = cg + G_CO*i;
                    float ga = gamma[co], be = beta[co];
                    #pragma unroll
                    for (int t = 0; t < TPT; t++) {
                        int tl = tg*TPT + t;
                        float v = (acc[i][t] - sMean[tl]) * sRstd[tl] * ga + be;
                        v = v > 0.f ? v : 0.2f*v;
                        out[((size_t)b*COUT + co)*T_LEN + t0 + tl] = v;
                    }
                }
            } else { // GLU
                constexpr int H = CPT/2;
                #pragma unroll
                for (int i = 0; i < H; i++) {
                    int co = cg + G_CO*i;
                    int co2 = co + COUT/2;
                    float ga = gamma[co], be = beta[co];
                    float g2a = gamma[co2], b2 = beta[co2];
                    #pragma unroll
                    for (int t = 0; t < TPT; t++) {
                        int tl = tg*TPT + t;
                        float m = sMean[tl], r = sRstd[tl];
                        float a  = (acc[i][t]   - m) * r * ga  + be;
                        float gt = (acc[i+H][t] - m) * r * g2a + b2;
                        out[((size_t)b*(COUT/2) + co)*T_LEN + t0 + tl] = a * (1.f/(1.f + expf(-gt)));
                    }
                }
            }
        } else if constexpr (EPI == 0) {
            #pragma unroll
            for (int i = 0; i < CPT; i++) {
                int co = cg + G_CO*i;
                #pragma unroll
                for (int t = 0; t < TPT; t++)
                    out[((size_t)b*COUT + co)*T_LEN + t0 + tg*TPT + t] = acc[i][t];
            }
        } else { // EPI == 4, transposed write [b][t][co]
            #pragma unroll
            for (int i = 0; i < CPT; i++) {
                int co = cg + G_CO*i;
                #pragma unroll
                for (int t = 0; t < TPT; t++) {
                    int tl = tg*TPT + t;
                    out[((size_t)b*T_LEN + t0 + tl)*COUT + co] = acc[i][t];
                }
            }
        }
    }
}

// ---------------- host launch helper ----------------
#define LAUNCH_CONV(CIN1,CIN2,COUT,KS,CIB,GCO,TPT,EPI, in1,in2,wtp,biasp,gap,bep,outp,oidxp) do { \
    constexpr int GT_ = 256/(GCO); constexpr int TT_ = GT_*(TPT); \
    constexpr int WE_ = (CIB)*(KS)*(COUT); \
    constexpr int IE_ = (CIB)*(TT_+(KS)-1); \
    constexpr int RED_ = ((EPI)==1||(EPI)==2||(EPI)==3) ? (2*TT_*((GCO)+1) + 2*TT_) : 0; \
    constexpr int SB_ = (WE_+IE_+RED_)*4; \
    auto kf_ = &conv_k<CIN1,CIN2,COUT,KS,CIB,GCO,TPT,EPI>; \
    if (SB_ > 48*1024) cudaFuncSetAttribute(kf_, cudaFuncAttributeMaxDynamicSharedMemorySize, SB_); \
    kf_<<<dim3(T_LEN/TT_, B_SZ), 256, SB_>>>(in1,in2,wtp,biasp,gap,bep,outp,oidxp); \
} while (0)

extern "C" void kernel_launch(void* const* d_in, const int* in_sizes, int n_in,
                              void* d_out, int out_size) {
    (void)in_sizes; (void)n_in; (void)out_size;
    const float* x       = (const float*)d_in[0];
    const int*   y       = (const int*)  d_in[1];
    const float* enc_w1  = (const float*)d_in[2];
    const float* enc_b1  = (const float*)d_in[3];
    const float* enc_g1  = (const float*)d_in[4];
    const float* enc_bt1 = (const float*)d_in[5];
    const float* enc_w2  = (const float*)d_in[6];
    const float* enc_b2  = (const float*)d_in[7];
    const float* enc_g2  = (const float*)d_in[8];
    const float* enc_bt2 = (const float*)d_in[9];
    const float* enc_w3  = (const float*)d_in[10];
    const float* enc_b3  = (const float*)d_in[11];
    const float* enc_g3  = (const float*)d_in[12];
    const float* enc_bt3 = (const float*)d_in[13];
    const float* mlp_w   = (const float*)d_in[14];
    const float* mlp_b   = (const float*)d_in[15];
    const float* codebook= (const float*)d_in[16];
    const float* spk_emb = (const float*)d_in[17];
    const float* dec_w1  = (const float*)d_in[18];
    const float* dec_b1  = (const float*)d_in[19];
    const float* dec_g1  = (const float*)d_in[20];
    const float* dec_bt1 = (const float*)d_in[21];
    const float* dec_w2  = (const float*)d_in[22];
    const float* dec_b2  = (const float*)d_in[23];
    const float* dec_g2  = (const float*)d_in[24];
    const float* dec_bt2 = (const float*)d_in[25];
    const float* dec_w3  = (const float*)d_in[26];
    const float* dec_b3  = (const float*)d_in[27];
    float* outp = (float*)d_out;

    float *bufA, *bufB, *ye, *z, *zvq, *wt, *cbt, *cbn, *spk; int* idx;
    cudaGetSymbolAddress((void**)&bufA, g_bufA);
    cudaGetSymbolAddress((void**)&bufB, g_bufB);
    cudaGetSymbolAddress((void**)&ye,   g_ye);
    cudaGetSymbolAddress((void**)&z,    g_z);
    cudaGetSymbolAddress((void**)&zvq,  g_zvq);
    cudaGetSymbolAddress((void**)&wt,   g_wt);
    cudaGetSymbolAddress((void**)&cbt,  g_cbt);
    cudaGetSymbolAddress((void**)&cbn,  g_cbn);
    cudaGetSymbolAddress((void**)&spk,  g_spk);
    cudaGetSymbolAddress((void**)&idx,  g_idx);

    // x [B,T,F] -> [B,F,T]
    transpose_x_k<<<dim3(T_LEN/32, 3, B_SZ), dim3(32,8)>>>(x, bufA);
    // speaker embedding: normalize + gather
    spknorm_k<<<128, 128>>>(spk_emb, spk);
    ye_gather_k<<<dim3(T_LEN/32, B_SZ), 256>>>(y, spk, ye);

    // encoder 1: 80 -> 512, LN + LeakyReLU
    wtrans_k<<<(512*80*5 + 255)/256, 256>>>(enc_w1, wt, 80, 512, 5, 0);
    LAUNCH_CONV(80,0,512,5, 8,64,8, 1, bufA, (const float*)nullptr, wt, enc_b1, enc_g1, enc_bt1, bufB, (int*)nullptr);
    // encoder 2
    wtrans_k<<<(512*512*5 + 255)/256, 256>>>(enc_w2, wt, 512, 512, 5, 0);
    LAUNCH_CONV(512,0,512,5, 8,64,8, 1, bufB, (const float*)nullptr, wt, enc_b2, enc_g2, enc_bt2, bufA, (int*)nullptr);
    // encoder 3
    wtrans_k<<<(512*512*5 + 255)/256, 256>>>(enc_w3, wt, 512, 512, 5, 0);
    LAUNCH_CONV(512,0,512,5, 8,64,8, 1, bufA, (const float*)nullptr, wt, enc_b3, enc_g3, enc_bt3, bufB, (int*)nullptr);
    // mlp 1x1: 512 -> 64
    wtrans_k<<<(512*64 + 255)/256, 256>>>(mlp_w, wt, 512, 64, 1, 0);
    LAUNCH_CONV(512,0,64,1, 16,32,8, 0, bufB, (const float*)nullptr, wt, mlp_b, (const float*)nullptr, (const float*)nullptr, z, (int*)nullptr);
    // VQ: argmin over 512 codes
    wtrans_k<<<(64*512 + 255)/256, 256>>>(codebook, cbt, 64, 512, 1, 0);
    cbnorm_k<<<4, 128>>>(codebook, cbn);
    LAUNCH_CONV(64,0,512,1, 16,64,8, 3, z, (const float*)nullptr, cbt, cbn, (const float*)nullptr, (const float*)nullptr, (float*)nullptr, idx);
    zvq_gather_k<<<dim3(T_LEN/32, B_SZ), 256>>>(idx, codebook, zvq);
    // decoder 1: (64 + 128) -> 1024, LN + GLU -> 512
    wtrans_k<<<(192*1024*5 + 255)/256, 256>>>(dec_w1, wt, 192, 1024, 5, 1);
    LAUNCH_CONV(64,128,1024,5, 4,128,8, 2, zvq, ye, wt, dec_b1, dec_g1, dec_bt1, bufA, (int*)nullptr);
    // decoder 2: (512 + 128) -> 1024, LN + GLU -> 512
    wtrans_k<<<(640*1024*5 + 255)/256, 256>>>(dec_w2, wt, 640, 1024, 5, 1);
    LAUNCH_CONV(512,128,1024,5, 4,128,8, 2, bufA, ye, wt, dec_b2, dec_g2, dec_bt2, bufB, (int*)nullptr);
    // decoder 3: (512 + 128) -> 80, transposed write to [B,T,F]
    wtrans_k<<<(640*80*5 + 255)/256, 256>>>(dec_w3, wt, 640, 80, 5, 1);
    LAUNCH_CONV(512,128,80,5, 8,16,4, 4, bufB, ye, wt, dec_b3, (const float*)nullptr, (const float*)nullptr, outp, (int*)nullptr);
}